// round 1
// baseline (speedup 1.0000x reference)
#include <cuda_runtime.h>

#define TOKENS 8192
#define DM     1024
#define LSEQ   2048
#define NB     4
#define NH     16
#define DK     64

// Scratch (device globals — no allocation in kernel_launch)
__device__ float g_h[TOKENS * DM];            // layernorm output
__device__ float g_qkv[(size_t)TOKENS * 3 * DM]; // qkv (rope applied in-place)
__device__ float g_o[TOKENS * DM];            // attention output

// ---------------------------------------------------------------------------
// LayerNorm: one block per row (1024 floats), 256 threads x float4
// ---------------------------------------------------------------------------
__global__ __launch_bounds__(256) void ln_kernel(const float* __restrict__ x,
                                                 float* __restrict__ h) {
    int row = blockIdx.x;
    int t = threadIdx.x;
    const float4* xr = (const float4*)(x + (size_t)row * DM);
    float4 v = xr[t];
    float s  = v.x + v.y + v.z + v.w;
    float ss = v.x * v.x + v.y * v.y + v.z * v.z + v.w * v.w;
    #pragma unroll
    for (int off = 16; off; off >>= 1) {
        s  += __shfl_xor_sync(0xffffffffu, s, off);
        ss += __shfl_xor_sync(0xffffffffu, ss, off);
    }
    __shared__ float sh[16];
    __shared__ float sh_mu, sh_r;
    int warp = t >> 5, lane = t & 31;
    if (lane == 0) { sh[warp] = s; sh[warp + 8] = ss; }
    __syncthreads();
    if (t == 0) {
        float S = 0.f, SS = 0.f;
        #pragma unroll
        for (int w = 0; w < 8; w++) { S += sh[w]; SS += sh[w + 8]; }
        float mu  = S * (1.0f / DM);
        float var = SS * (1.0f / DM) - mu * mu;
        sh_mu = mu;
        sh_r  = rsqrtf(var + 1e-8f);
    }
    __syncthreads();
    float mu = sh_mu, r = sh_r;
    float4 o = make_float4((v.x - mu) * r, (v.y - mu) * r,
                           (v.z - mu) * r, (v.w - mu) * r);
    ((float4*)(h + (size_t)row * DM))[t] = o;
}

// ---------------------------------------------------------------------------
// NT SGEMM: C[M,N] = A[M,K] * B[N,K]^T   (both row-major, K contiguous)
// 128x128x16 tile, 256 threads, 8x8 per-thread register tile.
// Shared tiles stored K-outer (transposed) so fragment loads are float4.
// ---------------------------------------------------------------------------
__global__ __launch_bounds__(256) void gemm_nt(const float* __restrict__ A,
                                               const float* __restrict__ Bm,
                                               float* __restrict__ C,
                                               int M, int N, int K) {
    const int BM = 128, BN = 128, BK = 16;
    __shared__ float As[BK][BM + 4];  // row stride 132 floats (16B-aligned)
    __shared__ float Bs[BK][BN + 4];
    int t  = threadIdx.x;
    int tx = t & 15, ty = t >> 4;
    int m0 = blockIdx.y * BM, n0 = blockIdx.x * BN;

    float acc[8][8];
    #pragma unroll
    for (int i = 0; i < 8; i++)
        #pragma unroll
        for (int j = 0; j < 8; j++) acc[i][j] = 0.f;

    for (int k0 = 0; k0 < K; k0 += BK) {
        #pragma unroll
        for (int r = 0; r < 2; r++) {
            int f   = t + r * 256;      // 0..511 float4 slots
            int row = f >> 2;           // 0..127
            int qd  = (f & 3) << 2;     // col quad 0,4,8,12
            float4 va = *(const float4*)(A + (size_t)(m0 + row) * K + k0 + qd);
            As[qd + 0][row] = va.x; As[qd + 1][row] = va.y;
            As[qd + 2][row] = va.z; As[qd + 3][row] = va.w;
            float4 vb = *(const float4*)(Bm + (size_t)(n0 + row) * K + k0 + qd);
            Bs[qd + 0][row] = vb.x; Bs[qd + 1][row] = vb.y;
            Bs[qd + 2][row] = vb.z; Bs[qd + 3][row] = vb.w;
        }
        __syncthreads();
        #pragma unroll
        for (int k = 0; k < BK; k++) {
            float ar[8], br[8];
            *(float4*)&ar[0] = *(float4*)&As[k][ty * 8];
            *(float4*)&ar[4] = *(float4*)&As[k][ty * 8 + 4];
            *(float4*)&br[0] = *(float4*)&Bs[k][tx * 8];
            *(float4*)&br[4] = *(float4*)&Bs[k][tx * 8 + 4];
            #pragma unroll
            for (int i = 0; i < 8; i++)
                #pragma unroll
                for (int j = 0; j < 8; j++) acc[i][j] += ar[i] * br[j];
        }
        __syncthreads();
    }
    #pragma unroll
    for (int i = 0; i < 8; i++) {
        float* cp = C + (size_t)(m0 + ty * 8 + i) * N + n0 + tx * 8;
        *(float4*)cp       = make_float4(acc[i][0], acc[i][1], acc[i][2], acc[i][3]);
        *(float4*)(cp + 4) = make_float4(acc[i][4], acc[i][5], acc[i][6], acc[i][7]);
    }
}

// ---------------------------------------------------------------------------
// RoPE (interleaved) applied in-place to q and k slices of g_qkv.
// One block per token (512 threads = 512 even/odd pairs per 1024-dim slice).
// Angle computed in double for an exact match with the fp32 reference path.
// ---------------------------------------------------------------------------
__global__ __launch_bounds__(512) void rope_kernel(float* __restrict__ qkv) {
    int token = blockIdx.x;
    int p = threadIdx.x;        // 0..511
    int head = p >> 5;          // /32  (DK/2 = 32 pairs per head)
    int i = p & 31;
    int l = token & (LSEQ - 1);
    double inv = pow(10000.0, -(double)i / 32.0);
    double ang = (double)l * inv;
    double snd, csd;
    sincos(ang, &snd, &csd);
    float sn = (float)snd, cs = (float)csd;
    size_t base = (size_t)token * 3 * DM + head * DK + 2 * i;
    float x1 = qkv[base], x2 = qkv[base + 1];
    qkv[base]     = x1 * cs - x2 * sn;
    qkv[base + 1] = x1 * sn + x2 * cs;
    float y1 = qkv[base + DM], y2 = qkv[base + DM + 1];
    qkv[base + DM]     = y1 * cs - y2 * sn;
    qkv[base + DM + 1] = y1 * sn + y2 * cs;
}

// ---------------------------------------------------------------------------
// Causal flash attention (fp32). One CTA = one (b, h, 64-row q tile).
// 256 threads; thread (ty,tx) owns a 4x4 fragment. All smem tiles padded to
// 68-float rows; Q/K/P stored transposed so fragment loads are float4.
// ---------------------------------------------------------------------------
__global__ __launch_bounds__(256) void flash_kernel(const float* __restrict__ qkv,
                                                    float* __restrict__ o) {
    extern __shared__ float sm[];
    float* Qs = sm;              // [d][q]  64x68
    float* Ks = sm + 64 * 68;    // [d][k]
    float* Vs = sm + 2 * 64 * 68; // [k][d]
    float* Ps = sm + 3 * 64 * 68; // [k][q]
    int t = threadIdx.x, tx = t & 15, ty = t >> 4;
    int qt = blockIdx.x, h = blockIdx.y, b = blockIdx.z;
    int q0 = qt * 64;

    const float* qbase = qkv + ((size_t)(b * LSEQ + q0)) * 3 * DM + h * DK;
    for (int f = t; f < 1024; f += 256) {           // 1024 float4 = 64x64 tile
        int row = f >> 4;
        int qd  = (f & 15) << 2;
        float4 v = *(const float4*)(qbase + (size_t)row * 3 * DM + qd);
        Qs[(qd + 0) * 68 + row] = v.x; Qs[(qd + 1) * 68 + row] = v.y;
        Qs[(qd + 2) * 68 + row] = v.z; Qs[(qd + 3) * 68 + row] = v.w;
    }

    float m[4], lsum[4], acc[4][4];
    #pragma unroll
    for (int i = 0; i < 4; i++) {
        m[i] = -1e30f; lsum[i] = 0.f;
        #pragma unroll
        for (int j = 0; j < 4; j++) acc[i][j] = 0.f;
    }

    for (int kt = 0; kt <= qt; kt++) {
        const float* kb = qkv + ((size_t)(b * LSEQ + kt * 64)) * 3 * DM + DM + h * DK;
        const float* vbp = kb + DM;
        for (int f = t; f < 1024; f += 256) {
            int row = f >> 4;
            int qd  = (f & 15) << 2;
            float4 kv4 = *(const float4*)(kb + (size_t)row * 3 * DM + qd);
            Ks[(qd + 0) * 68 + row] = kv4.x; Ks[(qd + 1) * 68 + row] = kv4.y;
            Ks[(qd + 2) * 68 + row] = kv4.z; Ks[(qd + 3) * 68 + row] = kv4.w;
            float4 vv4 = *(const float4*)(vbp + (size_t)row * 3 * DM + qd);
            *(float4*)&Vs[row * 68 + qd] = vv4;
        }
        __syncthreads();

        // S = (Q K^T) * scale
        float s[4][4];
        #pragma unroll
        for (int i = 0; i < 4; i++)
            #pragma unroll
            for (int j = 0; j < 4; j++) s[i][j] = 0.f;
        #pragma unroll 4
        for (int d = 0; d < 64; d++) {
            float4 qa = *(float4*)&Qs[d * 68 + ty * 4];
            float4 ka = *(float4*)&Ks[d * 68 + tx * 4];
            float qv[4] = {qa.x, qa.y, qa.z, qa.w};
            float kv[4] = {ka.x, ka.y, ka.z, ka.w};
            #pragma unroll
            for (int i = 0; i < 4; i++)
                #pragma unroll
                for (int j = 0; j < 4; j++) s[i][j] += qv[i] * kv[j];
        }
        const float scale = 0.125f;  // 1/sqrt(64)
        bool diag = (kt == qt);
        #pragma unroll
        for (int i = 0; i < 4; i++)
            #pragma unroll
            for (int j = 0; j < 4; j++) {
                s[i][j] *= scale;
                if (diag && (tx * 4 + j) > (ty * 4 + i)) s[i][j] = -1e30f;
            }

        // streaming softmax
        float mi[4];
        #pragma unroll
        for (int i = 0; i < 4; i++)
            mi[i] = fmaxf(fmaxf(s[i][0], s[i][1]), fmaxf(s[i][2], s[i][3]));
        #pragma unroll
        for (int off = 8; off; off >>= 1)
            #pragma unroll
            for (int i = 0; i < 4; i++)
                mi[i] = fmaxf(mi[i], __shfl_xor_sync(0xffffffffu, mi[i], off));
        float alpha[4], rs[4];
        #pragma unroll
        for (int i = 0; i < 4; i++) {
            float mn = fmaxf(m[i], mi[i]);
            alpha[i] = __expf(m[i] - mn);
            m[i] = mn;
            rs[i] = 0.f;
            #pragma unroll
            for (int j = 0; j < 4; j++) {
                s[i][j] = __expf(s[i][j] - mn);
                rs[i] += s[i][j];
            }
        }
        #pragma unroll
        for (int off = 8; off; off >>= 1)
            #pragma unroll
            for (int i = 0; i < 4; i++)
                rs[i] += __shfl_xor_sync(0xffffffffu, rs[i], off);
        #pragma unroll
        for (int i = 0; i < 4; i++) {
            lsum[i] = lsum[i] * alpha[i] + rs[i];
            #pragma unroll
            for (int j = 0; j < 4; j++) acc[i][j] *= alpha[i];
        }
        // publish P (transposed [k][q])
        #pragma unroll
        for (int i = 0; i < 4; i++)
            #pragma unroll
            for (int j = 0; j < 4; j++)
                Ps[(tx * 4 + j) * 68 + ty * 4 + i] = s[i][j];
        __syncthreads();

        // O += P V
        #pragma unroll 4
        for (int kk = 0; kk < 64; kk++) {
            float4 pa = *(float4*)&Ps[kk * 68 + ty * 4];
            float4 va = *(float4*)&Vs[kk * 68 + tx * 4];
            float pv[4] = {pa.x, pa.y, pa.z, pa.w};
            float vv[4] = {va.x, va.y, va.z, va.w};
            #pragma unroll
            for (int i = 0; i < 4; i++)
                #pragma unroll
                for (int j = 0; j < 4; j++) acc[i][j] += pv[i] * vv[j];
        }
        __syncthreads();
    }

    #pragma unroll
    for (int i = 0; i < 4; i++) {
        int token = b * LSEQ + q0 + ty * 4 + i;
        float inv = 1.0f / lsum[i];
        float* op = o + (size_t)token * DM + h * DK + tx * 4;
        *(float4*)op = make_float4(acc[i][0] * inv, acc[i][1] * inv,
                                   acc[i][2] * inv, acc[i][3] * inv);
    }
}

// ---------------------------------------------------------------------------
extern "C" void kernel_launch(void* const* d_in, const int* in_sizes, int n_in,
                              void* d_out, int out_size) {
    const float* x    = (const float*)d_in[0];
    const float* W_in = (const float*)d_in[1];
    const float* W_o  = (const float*)d_in[2];
    float* out = (float*)d_out;

    float *h, *qkv, *o;
    cudaGetSymbolAddress((void**)&h,   g_h);
    cudaGetSymbolAddress((void**)&qkv, g_qkv);
    cudaGetSymbolAddress((void**)&o,   g_o);

    const int FLASH_SMEM = 4 * 64 * 68 * 4;  // 69632 B
    cudaFuncSetAttribute(flash_kernel, cudaFuncAttributeMaxDynamicSharedMemorySize,
                         FLASH_SMEM);

    ln_kernel<<<TOKENS, 256>>>(x, h);

    dim3 g1(3 * DM / 128, TOKENS / 128);
    gemm_nt<<<g1, 256>>>(h, W_in, qkv, TOKENS, 3 * DM, DM);

    rope_kernel<<<TOKENS, 512>>>(qkv);

    dim3 g2(LSEQ / 64, NH, NB);
    flash_kernel<<<g2, 256, FLASH_SMEM>>>(qkv, o);

    dim3 g3(DM / 128, TOKENS / 128);
    gemm_nt<<<g3, 256>>>(o, W_o, out, TOKENS, DM, DM);
}